// round 1
// baseline (speedup 1.0000x reference)
#include <cuda_runtime.h>
#include <cuda_bf16.h>

// Problem constants
#define B_ROWS 16384
#define DIN 512
#define DOUT 512
#define NE 8
#define GCOLS 2

// GEMM tiling
#define TM 128
#define TN 128
#define TK 16
#define MAXT (B_ROWS / TM + NE)   // 136: upper bound on total (expert,row-tile) pairs

// ---------- device scratch (no allocation allowed) ----------
__device__ int g_counts[NE];
__device__ int g_offsets[NE];
__device__ int g_fill[NE];
__device__ int g_rowidx[B_ROWS];
__device__ int g_tile_expert[MAXT];
__device__ int g_tile_rowbase[MAXT];
__device__ int g_tile_rows[MAXT];

// ---------- f32x2 packed-FMA helpers (FFMA2: full-rate fp32 on sm_103a) ----------
__device__ __forceinline__ unsigned long long pack2(float lo, float hi) {
    unsigned long long r;
    asm("mov.b64 %0, {%1, %2};" : "=l"(r) : "f"(lo), "f"(hi));
    return r;
}
__device__ __forceinline__ void unpack2(unsigned long long v, float& lo, float& hi) {
    asm("mov.b64 {%0, %1}, %2;" : "=f"(lo), "=f"(hi) : "l"(v));
}
__device__ __forceinline__ void fma2(unsigned long long& d, unsigned long long a,
                                     unsigned long long b) {
    asm("fma.rn.f32x2 %0, %1, %2, %0;" : "+l"(d) : "l"(a), "l"(b));
}

// ---------- bucketing kernels ----------
__global__ void reset_kernel() {
    int t = threadIdx.x;
    if (t < NE) { g_counts[t] = 0; g_fill[t] = 0; }
}

__global__ void hist_kernel(const int* __restrict__ groups) {
    __shared__ int s[NE];
    if (threadIdx.x < NE) s[threadIdx.x] = 0;
    __syncthreads();
    for (int b = blockIdx.x * blockDim.x + threadIdx.x; b < B_ROWS;
         b += gridDim.x * blockDim.x) {
        atomicAdd(&s[groups[b * GCOLS]], 1);
    }
    __syncthreads();
    if (threadIdx.x < NE) atomicAdd(&g_counts[threadIdx.x], s[threadIdx.x]);
}

__global__ void scan_kernel() {
    if (threadIdx.x == 0) {
        int total = 0, t = 0;
        for (int e = 0; e < NE; e++) {
            g_offsets[e] = total;
            int cnt = g_counts[e];
            for (int s = 0; s < cnt; s += TM) {
                g_tile_expert[t]  = e;
                g_tile_rowbase[t] = total + s;
                g_tile_rows[t]    = (cnt - s < TM) ? (cnt - s) : TM;
                t++;
            }
            total += cnt;
        }
        for (; t < MAXT; t++) g_tile_expert[t] = -1;
    }
}

__global__ void scatter_kernel(const int* __restrict__ groups) {
    int b = blockIdx.x * blockDim.x + threadIdx.x;
    if (b < B_ROWS) {
        int e = groups[b * GCOLS];
        int pos = g_offsets[e] + atomicAdd(&g_fill[e], 1);
        g_rowidx[pos] = b;
    }
}

// ---------- grouped SGEMM: out[rows] = x[rows] @ W[e] + bias[e] ----------
// Block: 256 threads, computes TM x TN tile. Each thread: 8 rows x 8 cols
// (as 4 row-pairs x 8 cols in packed f32x2 accumulators).
__global__ __launch_bounds__(256)
void gemm_kernel(const float* __restrict__ x, const float* __restrict__ W,
                 const float* __restrict__ bias, float* __restrict__ out) {
    const int t = blockIdx.x;
    const int e = g_tile_expert[t];
    if (e < 0) return;
    const int rowbase = g_tile_rowbase[t];
    const int rows    = g_tile_rows[t];
    const int n0      = blockIdx.y * TN;

    __shared__ float xs[2][TK][TM];
    __shared__ float ws[2][TK][TN];
    __shared__ int   srows[TM];

    const int tid = threadIdx.x;

    if (tid < TM) srows[tid] = (tid < rows) ? g_rowidx[rowbase + tid] : -1;
    __syncthreads();

    // x loader: thread handles (m = tid&127, k-octet = tid>>7)
    const int lm  = tid & 127;
    const int lks = (tid >> 7) * 8;
    int lr = srows[lm]; if (lr < 0) lr = 0;
    const float* xp = x + (size_t)lr * DIN + lks;

    // W loader: thread handles (k = tid>>4, 8 cols at n = (tid&15)*8)
    const int wk = tid >> 4;
    const int wn = (tid & 15) * 8;
    const float* wp = W + (size_t)e * DIN * DOUT + (size_t)wk * DOUT + n0 + wn;

    // compute coords: 16x16 thread grid, 8x8 micro-tile
    const int tr = tid >> 4;   // row group: rows tr*8 .. tr*8+7
    const int tc = tid & 15;   // col group: cols tc*8 .. tc*8+7

    unsigned long long acc[4][8];
#pragma unroll
    for (int rp = 0; rp < 4; rp++)
#pragma unroll
        for (int c = 0; c < 8; c++) acc[rp][c] = 0ULL;

    float4 xa, xb, wa, wb;

    // prologue: stage 0
    xa = *(const float4*)(xp);
    xb = *(const float4*)(xp + 4);
    wa = *(const float4*)(wp);
    wb = *(const float4*)(wp + 4);
    {
        // store to buffer 0
        xs[0][lks + 0][lm] = xa.x; xs[0][lks + 1][lm] = xa.y;
        xs[0][lks + 2][lm] = xa.z; xs[0][lks + 3][lm] = xa.w;
        xs[0][lks + 4][lm] = xb.x; xs[0][lks + 5][lm] = xb.y;
        xs[0][lks + 6][lm] = xb.z; xs[0][lks + 7][lm] = xb.w;
        *(float4*)&ws[0][wk][wn]     = wa;
        *(float4*)&ws[0][wk][wn + 4] = wb;
    }
    __syncthreads();

    const int NST = DIN / TK;  // 32 stages
    for (int kt = 0; kt < NST; ++kt) {
        const int buf = kt & 1;
        if (kt + 1 < NST) {
            const float* xpn = xp + (kt + 1) * TK;
            xa = *(const float4*)(xpn);
            xb = *(const float4*)(xpn + 4);
            const float* wpn = wp + (size_t)(kt + 1) * TK * DOUT;
            wa = *(const float4*)(wpn);
            wb = *(const float4*)(wpn + 4);
        }

#pragma unroll
        for (int k = 0; k < TK; k++) {
            // a: 8 rows read as 4 packed pairs (rows contiguous in xs[k][m])
            const ulonglong2 a01 = *(const ulonglong2*)&xs[buf][k][tr * 8];
            const ulonglong2 a23 = *(const ulonglong2*)&xs[buf][k][tr * 8 + 4];
            unsigned long long aa[4] = {a01.x, a01.y, a23.x, a23.y};
            // b: 8 cols, each duplicated into both lanes
            const float4 b0 = *(const float4*)&ws[buf][k][tc * 8];
            const float4 b1 = *(const float4*)&ws[buf][k][tc * 8 + 4];
            unsigned long long bb[8];
            bb[0] = pack2(b0.x, b0.x); bb[1] = pack2(b0.y, b0.y);
            bb[2] = pack2(b0.z, b0.z); bb[3] = pack2(b0.w, b0.w);
            bb[4] = pack2(b1.x, b1.x); bb[5] = pack2(b1.y, b1.y);
            bb[6] = pack2(b1.z, b1.z); bb[7] = pack2(b1.w, b1.w);
#pragma unroll
            for (int rp = 0; rp < 4; rp++)
#pragma unroll
                for (int c = 0; c < 8; c++) fma2(acc[rp][c], aa[rp], bb[c]);
        }

        if (kt + 1 < NST) {
            const int nb = 1 - buf;
            xs[nb][lks + 0][lm] = xa.x; xs[nb][lks + 1][lm] = xa.y;
            xs[nb][lks + 2][lm] = xa.z; xs[nb][lks + 3][lm] = xa.w;
            xs[nb][lks + 4][lm] = xb.x; xs[nb][lks + 5][lm] = xb.y;
            xs[nb][lks + 6][lm] = xb.z; xs[nb][lks + 7][lm] = xb.w;
            *(float4*)&ws[nb][wk][wn]     = wa;
            *(float4*)&ws[nb][wk][wn + 4] = wb;
            __syncthreads();
        }
    }

    // epilogue: add bias, scatter rows to out
    float bias_r[8];
    *(float4*)&bias_r[0] = *(const float4*)&bias[e * DOUT + n0 + tc * 8];
    *(float4*)&bias_r[4] = *(const float4*)&bias[e * DOUT + n0 + tc * 8 + 4];

#pragma unroll
    for (int rp = 0; rp < 4; rp++) {
        float vlo[8], vhi[8];
#pragma unroll
        for (int c = 0; c < 8; c++) {
            unpack2(acc[rp][c], vlo[c], vhi[c]);
            vlo[c] += bias_r[c];
            vhi[c] += bias_r[c];
        }
        const int m0 = tr * 8 + rp * 2;
        const int r0 = srows[m0];
        const int r1 = srows[m0 + 1];
        if (r0 >= 0) {
            float* o = out + (size_t)r0 * DOUT + n0 + tc * 8;
            *(float4*)(o)     = make_float4(vlo[0], vlo[1], vlo[2], vlo[3]);
            *(float4*)(o + 4) = make_float4(vlo[4], vlo[5], vlo[6], vlo[7]);
        }
        if (r1 >= 0) {
            float* o = out + (size_t)r1 * DOUT + n0 + tc * 8;
            *(float4*)(o)     = make_float4(vhi[0], vhi[1], vhi[2], vhi[3]);
            *(float4*)(o + 4) = make_float4(vhi[4], vhi[5], vhi[6], vhi[7]);
        }
    }
}

// ---------- launch ----------
extern "C" void kernel_launch(void* const* d_in, const int* in_sizes, int n_in,
                              void* d_out, int out_size) {
    const float* x      = (const float*)d_in[0];
    const int*   groups = (const int*)d_in[1];
    const float* W      = (const float*)d_in[2];
    const float* bias   = (const float*)d_in[3];
    float*       out    = (float*)d_out;

    reset_kernel<<<1, 32>>>();
    hist_kernel<<<128, 256>>>(groups);
    scan_kernel<<<1, 32>>>();
    scatter_kernel<<<B_ROWS / 256, 256>>>(groups);

    dim3 grid(MAXT, DOUT / TN);
    gemm_kernel<<<grid, 256>>>(x, W, bias, out);
}

// round 3
// speedup vs baseline: 2.2084x; 2.2084x over previous
#include <cuda_runtime.h>
#include <cuda_bf16.h>
#include <cstdint>

// ---------------- problem constants ----------------
#define B_ROWS 16384
#define DIN 512
#define DOUT 512
#define NE 8
#define GCOLS 2

// ---------------- GEMM tiling ----------------
#define TM 128
#define TN 128
#define TK 32
#define NSTAGE (DIN / TK)          // 16
#define MAXT (B_ROWS / TM + NE)    // 136

#define SA 40    // A smem row stride (elems), 80B: conflict-free ldmatrix
#define SB 136   // B smem row stride (elems), 272B

// per-buffer smem offsets (bytes)
#define AHI 0
#define ALO (TM * SA * 2)                 // 10240
#define BHI (2 * TM * SA * 2)             // 20480
#define BLO (2 * TM * SA * 2 + TK * SB * 2)  // 29184
#define BUF_BYTES (2 * TM * SA * 2 + 2 * TK * SB * 2)  // 37888
#define OFF_BUF 512                        // after srows[128]
#define GEMM_SMEM (OFF_BUF + 2 * BUF_BYTES)  // 76288

// ---------------- device scratch ----------------
__device__ int g_counts[NE];
__device__ int g_offsets[NE];
__device__ int g_fill[NE];
__device__ int g_rowidx[B_ROWS];
__device__ int g_tile_expert[MAXT];
__device__ int g_tile_rowbase[MAXT];
__device__ int g_tile_rows[MAXT];

// ---------------- helpers ----------------
__device__ __forceinline__ uint32_t smem_u32(const void* p) {
    uint32_t a;
    asm("{ .reg .u64 t; cvta.to.shared.u64 t, %1; cvt.u32.u64 %0, t; }" : "=r"(a) : "l"(p));
    return a;
}

__device__ __forceinline__ void ldsm_x4(uint32_t* r, uint32_t addr) {
    asm volatile("ldmatrix.sync.aligned.m8n8.x4.shared.b16 {%0,%1,%2,%3}, [%4];"
                 : "=r"(r[0]), "=r"(r[1]), "=r"(r[2]), "=r"(r[3]) : "r"(addr));
}
__device__ __forceinline__ void ldsm_x4_t(uint32_t* r, uint32_t addr) {
    asm volatile("ldmatrix.sync.aligned.m8n8.x4.trans.shared.b16 {%0,%1,%2,%3}, [%4];"
                 : "=r"(r[0]), "=r"(r[1]), "=r"(r[2]), "=r"(r[3]) : "r"(addr));
}
__device__ __forceinline__ void mma_bf16(float* c, const uint32_t* a, const uint32_t* b) {
    asm volatile(
        "mma.sync.aligned.m16n8k16.row.col.f32.bf16.bf16.f32 "
        "{%0,%1,%2,%3}, {%4,%5,%6,%7}, {%8,%9}, {%0,%1,%2,%3};"
        : "+f"(c[0]), "+f"(c[1]), "+f"(c[2]), "+f"(c[3])
        : "r"(a[0]), "r"(a[1]), "r"(a[2]), "r"(a[3]), "r"(b[0]), "r"(b[1]));
}

// split pair of floats into packed bf16 (hi) and packed bf16 (residual lo)
__device__ __forceinline__ void split2(float a, float b, uint32_t& h, uint32_t& l) {
    __nv_bfloat162 hv = __floats2bfloat162_rn(a, b);
    float2 hf = __bfloat1622float2(hv);
    __nv_bfloat162 lv = __floats2bfloat162_rn(a - hf.x, b - hf.y);
    h = *reinterpret_cast<uint32_t*>(&hv);
    l = *reinterpret_cast<uint32_t*>(&lv);
}

// convert 16 floats (4 float4) -> 2x uint4 (hi, lo) and store to smem
__device__ __forceinline__ void cvt_store16(const float4* v, char* shi, char* slo) {
    uint4 H0, L0, H1, L1;
    split2(v[0].x, v[0].y, H0.x, L0.x);
    split2(v[0].z, v[0].w, H0.y, L0.y);
    split2(v[1].x, v[1].y, H0.z, L0.z);
    split2(v[1].z, v[1].w, H0.w, L0.w);
    split2(v[2].x, v[2].y, H1.x, L1.x);
    split2(v[2].z, v[2].w, H1.y, L1.y);
    split2(v[3].x, v[3].y, H1.z, L1.z);
    split2(v[3].z, v[3].w, H1.w, L1.w);
    *(uint4*)(shi)      = H0;
    *(uint4*)(shi + 16) = H1;
    *(uint4*)(slo)      = L0;
    *(uint4*)(slo + 16) = L1;
}

// ---------------- bucketing ----------------
__global__ void reset_kernel() {
    int t = threadIdx.x;
    if (t < NE) { g_counts[t] = 0; g_fill[t] = 0; }
}

__global__ void hist_kernel(const int* __restrict__ groups) {
    __shared__ int s[NE];
    if (threadIdx.x < NE) s[threadIdx.x] = 0;
    __syncthreads();
    for (int b = blockIdx.x * blockDim.x + threadIdx.x; b < B_ROWS;
         b += gridDim.x * blockDim.x)
        atomicAdd(&s[groups[b * GCOLS]], 1);
    __syncthreads();
    if (threadIdx.x < NE) atomicAdd(&g_counts[threadIdx.x], s[threadIdx.x]);
}

__global__ void scan_kernel() {
    if (threadIdx.x == 0) {
        int total = 0, t = 0;
        for (int e = 0; e < NE; e++) {
            g_offsets[e] = total;
            int cnt = g_counts[e];
            for (int s = 0; s < cnt; s += TM) {
                g_tile_expert[t]  = e;
                g_tile_rowbase[t] = total + s;
                g_tile_rows[t]    = (cnt - s < TM) ? (cnt - s) : TM;
                t++;
            }
            total += cnt;
        }
        for (; t < MAXT; t++) g_tile_expert[t] = -1;
    }
}

__global__ void scatter_kernel(const int* __restrict__ groups) {
    int b = blockIdx.x * blockDim.x + threadIdx.x;
    int e = groups[b * GCOLS];
    int lane = threadIdx.x & 31;
    unsigned mask = __match_any_sync(0xffffffffu, e);
    int leader = __ffs(mask) - 1;
    int prefix = __popc(mask & ((1u << lane) - 1));
    int base = 0;
    if (lane == leader) base = atomicAdd(&g_fill[e], __popc(mask));
    base = __shfl_sync(0xffffffffu, base, leader);
    g_rowidx[g_offsets[e] + base + prefix] = b;
}

// ---------------- grouped GEMM via mma.sync (bf16 3-term split) ----------------
__global__ __launch_bounds__(256, 1)
void gemm_mma(const float* __restrict__ x, const float* __restrict__ W,
              const float* __restrict__ bias, float* __restrict__ out) {
    const int tile = blockIdx.x;
    const int e = g_tile_expert[tile];
    if (e < 0) return;
    const int rowbase = g_tile_rowbase[tile];
    const int rows    = g_tile_rows[tile];
    const int n0      = blockIdx.y * TN;

    extern __shared__ char sm[];
    int* srows = (int*)sm;
    const uint32_t smu = smem_u32(sm);

    const int tid  = threadIdx.x;
    const int lane = tid & 31;
    const int wid  = tid >> 5;

    if (tid < TM) srows[tid] = (tid < rows) ? g_rowidx[rowbase + tid] : -1;
    __syncthreads();

    // ---- loader slots ----
    // A: thread -> (row = tid>>1, k-half = (tid&1)*16)
    const int arow = tid >> 1;
    const int akh  = (tid & 1) * 16;
    int asrc = srows[arow]; if (asrc < 0) asrc = 0;
    const float* aptr = x + (size_t)asrc * DIN + akh;
    const int a_sts = (arow * SA + akh) * 2;  // byte offset within buffer

    // B: thread -> (k row = tid>>3, n-chunk = (tid&7)*16)
    const int brow = tid >> 3;
    const int bcol = (tid & 7) * 16;
    const float* bptr = W + ((size_t)e * DIN + brow) * DOUT + n0 + bcol;
    const int b_sts = (brow * SB + bcol) * 2;

    // ---- warp compute coords ----
    const int m0w = (wid >> 1) * 32;   // warp M origin within tile
    const int n0w = (wid & 1) * 64;    // warp N origin within tile
    const int lr = (lane & 7) + ((lane >> 3) & 1) * 8;  // ldmatrix row idx 0..15
    const int lc = (lane >> 4) * 8;                      // ldmatrix col half
    const int a_lm_base = ((m0w + lr) * SA + lc) * 2;    // + (mt*16*SA + ks)*2
    const int b_lm_base = (lr * SB + n0w + lc) * 2;      // + (ks*SB + p*16)*2

    float c[2][8][4];
#pragma unroll
    for (int mt = 0; mt < 2; mt++)
#pragma unroll
        for (int nt = 0; nt < 8; nt++)
#pragma unroll
            for (int j = 0; j < 4; j++) c[mt][nt][j] = 0.f;

    float4 av[4], bv[4];

    // preload stage 0
#pragma unroll
    for (int j = 0; j < 4; j++) av[j] = *(const float4*)(aptr + j * 4);
#pragma unroll
    for (int j = 0; j < 4; j++) bv[j] = *(const float4*)(bptr + j * 4);
    {
        char* base = sm + OFF_BUF;
        cvt_store16(av, base + AHI + a_sts, base + ALO + a_sts);
        cvt_store16(bv, base + BHI + b_sts, base + BLO + b_sts);
    }

    for (int kt = 0; kt < NSTAGE; kt++) {
        __syncthreads();
        const int buf = kt & 1;
        const uint32_t bb = smu + OFF_BUF + buf * BUF_BYTES;

        // issue next-stage global loads early
        if (kt + 1 < NSTAGE) {
            const float* ap = aptr + (kt + 1) * TK;
#pragma unroll
            for (int j = 0; j < 4; j++) av[j] = *(const float4*)(ap + j * 4);
            const float* bp = W + ((size_t)e * DIN + (kt + 1) * TK + brow) * DOUT + n0 + bcol;
#pragma unroll
            for (int j = 0; j < 4; j++) bv[j] = *(const float4*)(bp + j * 4);
        }

        // compute on current buffer: two k16 steps
#pragma unroll
        for (int ks = 0; ks < 2; ks++) {
            const int kso = ks * 16;
            uint32_t ah[2][4], al[2][4];
#pragma unroll
            for (int mt = 0; mt < 2; mt++) {
                uint32_t ao = bb + a_lm_base + (mt * 16 * SA + kso) * 2;
                ldsm_x4(ah[mt], ao + AHI);
                ldsm_x4(al[mt], ao + ALO);
            }
            uint32_t bh[4][4], bl[4][4];
#pragma unroll
            for (int p = 0; p < 4; p++) {
                uint32_t bo = bb + b_lm_base + (kso * SB + p * 16) * 2;
                ldsm_x4_t(bh[p], bo + BHI);
                ldsm_x4_t(bl[p], bo + BLO);
            }
#pragma unroll
            for (int mt = 0; mt < 2; mt++)
#pragma unroll
                for (int p = 0; p < 4; p++) {
                    mma_bf16(c[mt][2 * p],     ah[mt], &bh[p][0]);
                    mma_bf16(c[mt][2 * p],     al[mt], &bh[p][0]);
                    mma_bf16(c[mt][2 * p],     ah[mt], &bl[p][0]);
                    mma_bf16(c[mt][2 * p + 1], ah[mt], &bh[p][2]);
                    mma_bf16(c[mt][2 * p + 1], al[mt], &bh[p][2]);
                    mma_bf16(c[mt][2 * p + 1], ah[mt], &bl[p][2]);
                }
        }

        // convert + store next stage into other buffer
        if (kt + 1 < NSTAGE) {
            char* nbase = sm + OFF_BUF + (1 - buf) * BUF_BYTES;
            cvt_store16(av, nbase + AHI + a_sts, nbase + ALO + a_sts);
            cvt_store16(bv, nbase + BHI + b_sts, nbase + BLO + b_sts);
        }
    }

    // ---- epilogue: bias + scattered stores ----
    const int rl = lane >> 2;          // row within m16 tile
    const int cl = (lane & 3) * 2;     // col pair within n8 tile
#pragma unroll
    for (int mt = 0; mt < 2; mt++) {
        const int lm0 = m0w + mt * 16 + rl;
        const int r0 = srows[lm0];
        const int r1 = srows[lm0 + 8];
#pragma unroll
        for (int nt = 0; nt < 8; nt++) {
            const int gcol = n0 + n0w + nt * 8 + cl;
            const float2 bv2 = *(const float2*)(bias + e * DOUT + gcol);
            if (r0 >= 0) {
                float2 v = make_float2(c[mt][nt][0] + bv2.x, c[mt][nt][1] + bv2.y);
                *(float2*)(out + (size_t)r0 * DOUT + gcol) = v;
            }
            if (r1 >= 0) {
                float2 v = make_float2(c[mt][nt][2] + bv2.x, c[mt][nt][3] + bv2.y);
                *(float2*)(out + (size_t)r1 * DOUT + gcol) = v;
            }
        }
    }
}

// ---------------- launch ----------------
extern "C" void kernel_launch(void* const* d_in, const int* in_sizes, int n_in,
                              void* d_out, int out_size) {
    const float* x      = (const float*)d_in[0];
    const int*   groups = (const int*)d_in[1];
    const float* W      = (const float*)d_in[2];
    const float* bias   = (const float*)d_in[3];
    float*       out    = (float*)d_out;

    cudaFuncSetAttribute(gemm_mma, cudaFuncAttributeMaxDynamicSharedMemorySize, GEMM_SMEM);

    reset_kernel<<<1, 32>>>();
    hist_kernel<<<64, 256>>>(groups);
    scan_kernel<<<1, 32>>>();
    scatter_kernel<<<B_ROWS / 256, 256>>>(groups);

    dim3 grid(MAXT, DOUT / TN);
    gemm_mma<<<grid, 256, GEMM_SMEM>>>(x, W, bias, out);
}